// round 15
// baseline (speedup 1.0000x reference)
#include <cuda_runtime.h>
#include <math.h>

#define NS 256   // time steps (s axis of output)
#define NB 512   // batch rows (l axis)
#define NH 128   // hidden / asset dim
#define NG 512   // 4*H gates

// ---------------- static device scratch (no allocations allowed) ----------------
__device__ float g_mean[NS];
__device__ float g_istd[NS];
__device__ float g_rowsumW[NG];                   // permuted column index
__device__ float g_bihP[NG];                      // permuted b_ih
__device__ float g_bhhP[NG];                      // permuted b_hh
__device__ float g_WihT[NH * NG];                 // [k][c]  (c = 4*asset+gate)
__device__ float g_Whh4[NH * NG];                 // [k>>2][c][k&3]  (float4-packed)
__device__ float g_xg[(size_t)NS * NB * NG];      // [t][b][c]
__device__ float g_hs[(size_t)NS * NB * NH];      // [t][b][a]
__device__ float g_Q[(size_t)NS * NH * NH];       // [s][a][c]

__device__ __forceinline__ float sigf(float x) { return 1.f / (1.f + expf(-x)); }
__device__ __forceinline__ float clamp1(float x) { return fminf(1.f, fmaxf(-1.f, x)); }

#define FMASK 0xffffffffu

__device__ __forceinline__ float warpSum(float v) {
#pragma unroll
    for (int o = 16; o > 0; o >>= 1) v += __shfl_xor_sync(FMASK, v, o);
    return v;
}
// 4-lane group reductions (xor offsets 1,2 stay within each quad)
__device__ __forceinline__ float grpSum4(float v) {
    v += __shfl_xor_sync(FMASK, v, 1);
    v += __shfl_xor_sync(FMASK, v, 2);
    return v;
}
__device__ __forceinline__ float grpMin4(float v) {
    v = fminf(v, __shfl_xor_sync(FMASK, v, 1));
    v = fminf(v, __shfl_xor_sync(FMASK, v, 2));
    return v;
}
__device__ __forceinline__ float grpMax4(float v) {
    v = fmaxf(v, __shfl_xor_sync(FMASK, v, 1));
    v = fmaxf(v, __shfl_xor_sync(FMASK, v, 2));
    return v;
}

// ---- packed f32x2 helpers (Blackwell FFMA2: 2 IEEE FMAs per instruction) ----
typedef unsigned long long ull2f;
union F4U { float4 v; ull2f u[2]; };

__device__ __forceinline__ ull2f ffma2(ull2f a, ull2f b, ull2f c) {
    ull2f d;
    asm("fma.rn.f32x2 %0, %1, %2, %3;" : "=l"(d) : "l"(a), "l"(b), "l"(c));
    return d;
}
__device__ __forceinline__ ull2f addf2(ull2f a, ull2f b) {
    ull2f d;
    asm("add.rn.f32x2 %0, %1, %2;" : "=l"(d) : "l"(a), "l"(b));
    return d;
}
__device__ __forceinline__ ull2f packf2(float lo, float hi) {
    ull2f o;
    asm("mov.b64 %0, {%1, %2};" : "=l"(o) : "f"(lo), "f"(hi));
    return o;
}
__device__ __forceinline__ ull2f dupf2(float x) {
    ull2f o;
    asm("mov.b64 %0, {%1, %1};" : "=l"(o) : "f"(x));
    return o;
}
__device__ __forceinline__ void unpackf2(ull2f p, float& lo, float& hi) {
    asm("mov.b64 {%0, %1}, %2;" : "=f"(lo), "=f"(hi) : "l"(p));
}

// ---------------- 1+2) fused: moments (blocks 0..255) + prep (blocks 256..511) --
// stored column c = 4*asset + gate   (orig column g = gate*128 + asset)
__global__ __launch_bounds__(256) void init_kernel(const float* __restrict__ x,
                                                   const float* __restrict__ Wih,
                                                   const float* __restrict__ Whh,
                                                   const float* __restrict__ b_ih,
                                                   const float* __restrict__ b_hh) {
    if (blockIdx.x < NS) {
        const int s = blockIdx.x;
        const float* xs = x + (size_t)s * (NB * NH);
        float sum = 0.f, sq = 0.f;
        for (int i = threadIdx.x; i < NB * NH; i += 256) {
            float v = xs[i];
            sum += v; sq += v * v;
        }
        __shared__ float s1[256], s2[256];
        s1[threadIdx.x] = sum; s2[threadIdx.x] = sq;
        __syncthreads();
        for (int o = 128; o > 0; o >>= 1) {
            if (threadIdx.x < o) {
                s1[threadIdx.x] += s1[threadIdx.x + o];
                s2[threadIdx.x] += s2[threadIdx.x + o];
            }
            __syncthreads();
        }
        if (threadIdx.x == 0) {
            const float invn = 1.f / (float)(NB * NH);
            float mean = s1[0] * invn;
            float var = s2[0] * invn - mean * mean;
            g_mean[s] = mean;
            g_istd[s] = 1.f / sqrtf(var + 1e-5f);
        }
    } else {
        int idx = (blockIdx.x - NS) * 256 + threadIdx.x;   // [0, 65536)
        int g = idx >> 7, k = idx & 127;
        int c = 4 * (g & 127) + (g >> 7);
        g_WihT[k * NG + c] = Wih[(size_t)g * NH + k];
        g_Whh4[(k >> 2) * (NG * 4) + c * 4 + (k & 3)] = Whh[(size_t)g * NH + k];
        if (idx < NG) {
            float s = 0.f;
            for (int kk = 0; kk < NH; kk++) s += Wih[(size_t)idx * NH + kk];
            int cc = 4 * (idx & 127) + (idx >> 7);
            g_rowsumW[cc] = s;
            g_bihP[cc] = b_ih[idx];
            g_bhhP[cc] = b_hh[idx];
        }
    }
}

// ---------------- 3) xg = IN(x) @ WihT + b_ih (IN folded into epilogue) --------
// 128x128 tile, 8x8 micro-tile via f32x2 packed FMA, k-step 16, 2 CTAs/SM.
__global__ __launch_bounds__(256, 2) void xg_gemm_kernel(const float* __restrict__ x,
                                                         const float* __restrict__ in_w,
                                                         const float* __restrict__ in_b) {
    __shared__ float As[16][132];   // [k][m]
    __shared__ float Bs[16][132];   // [k][c]
    const int m0 = blockIdx.x * 128;
    const int g0 = blockIdx.y * 128;
    const int tid = threadIdx.x;
    const int tx = tid & 15, ty = tid >> 4;
    ull2f acc2[8][4];
#pragma unroll
    for (int i = 0; i < 8; i++)
#pragma unroll
        for (int j = 0; j < 4; j++) acc2[i][j] = 0ull;   // (0.f, 0.f)

    for (int k0 = 0; k0 < 128; k0 += 16) {
#pragma unroll
        for (int r = 0; r < 2; r++) {
            int li = tid + r * 256;            // [0,512): A = 128 rows x 16 k
            int row = li >> 2, c4 = li & 3;
            float4 v = *(const float4*)(x + (size_t)(m0 + row) * NH + k0 + c4 * 4);
            As[c4 * 4 + 0][row] = v.x;
            As[c4 * 4 + 1][row] = v.y;
            As[c4 * 4 + 2][row] = v.z;
            As[c4 * 4 + 3][row] = v.w;
        }
#pragma unroll
        for (int r = 0; r < 2; r++) {
            int li = tid + r * 256;            // [0,512): B = 16 k x 128 c
            int kk = li >> 5, g4 = li & 31;
            float4 v = *(const float4*)(g_WihT + (size_t)(k0 + kk) * NG + g0 + g4 * 4);
            *(float4*)&Bs[kk][g4 * 4] = v;
        }
        __syncthreads();
#pragma unroll
        for (int k = 0; k < 16; k++) {
            float av[8];
            *(float4*)&av[0] = *(const float4*)&As[k][ty * 8];
            *(float4*)&av[4] = *(const float4*)&As[k][ty * 8 + 4];
            F4U b0_, b1_;
            b0_.v = *(const float4*)&Bs[k][tx * 4];
            b1_.v = *(const float4*)&Bs[k][64 + tx * 4];
            ull2f bv2[4] = { b0_.u[0], b0_.u[1], b1_.u[0], b1_.u[1] };
#pragma unroll
            for (int i = 0; i < 8; i++) {
                ull2f ad = dupf2(av[i]);
#pragma unroll
                for (int j = 0; j < 4; j++) acc2[i][j] = ffma2(ad, bv2[j], acc2[i][j]);
            }
        }
        __syncthreads();
    }
    const int s = m0 >> 9;                      // 512 rows per time step
    const float iw = in_w[0], ib = in_b[0];
    const float alpha = iw * g_istd[s];
    const float gamma = ib - alpha * g_mean[s];
    float base[8];
#pragma unroll
    for (int j = 0; j < 8; j++) {
        int gi = (j < 4) ? (g0 + tx * 4 + j) : (g0 + 64 + tx * 4 + (j - 4));
        base[j] = gamma * g_rowsumW[gi] + g_bihP[gi];
    }
#pragma unroll
    for (int i = 0; i < 8; i++) {
        int m = m0 + ty * 8 + i;
        float a0, a1, a2, a3, a4, a5, a6, a7;
        unpackf2(acc2[i][0], a0, a1);
        unpackf2(acc2[i][1], a2, a3);
        unpackf2(acc2[i][2], a4, a5);
        unpackf2(acc2[i][3], a6, a7);
        float4 o0, o1;
        o0.x = fmaf(alpha, a0, base[0]);
        o0.y = fmaf(alpha, a1, base[1]);
        o0.z = fmaf(alpha, a2, base[2]);
        o0.w = fmaf(alpha, a3, base[3]);
        o1.x = fmaf(alpha, a4, base[4]);
        o1.y = fmaf(alpha, a5, base[5]);
        o1.z = fmaf(alpha, a6, base[6]);
        o1.w = fmaf(alpha, a7, base[7]);
        *(float4*)(g_xg + (size_t)m * NG + g0 + tx * 4) = o0;
        *(float4*)(g_xg + (size_t)m * NG + g0 + 64 + tx * 4) = o1;
    }
}

// ---------------- 4) LSTM: 4 rows/CTA, gate-interleaved, xg prefetch -----------
__global__ __launch_bounds__(512) void lstm_kernel() {
    const int b0 = blockIdx.x * 4;
    const int c = threadIdx.x;                 // permuted column 0..511
    const int lane = c & 31;
    const int kr = lane & 3;                   // row this lane activates
    const int asset = c >> 2;                  // asset this lane activates
    __shared__ float2 h2[2][2][128];           // [buf][rowpair][k]
    ((float*)h2[0])[(kr >> 1) * 256 + asset * 2 + (kr & 1)] = 0.f;
    float c_reg = 0.f;
    const float bhh = g_bhhP[c];
    const float4* __restrict__ w4 = ((const float4*)g_Whh4) + c;   // row k4: +k4*NG
    __syncthreads();

    // prefetch xg for t = 0
    float x0, x1, x2, x3;
    {
        const float* xp = g_xg + (size_t)b0 * NG + c;
        x0 = xp[0]; x1 = xp[NG]; x2 = xp[2 * NG]; x3 = xp[3 * NG];
    }

    for (int t = 0; t < NS; t++) {
        const int p = t & 1;
        ull2f acc01 = packf2(x0 + bhh, x1 + bhh);
        ull2f acc23 = packf2(x2 + bhh, x3 + bhh);
        // issue next step's xg loads now; consumed after the barrier
        {
            int tn = (t + 1 < NS) ? t + 1 : t;
            const float* xp = g_xg + ((size_t)tn * NB + b0) * NG + c;
            x0 = xp[0]; x1 = xp[NG]; x2 = xp[2 * NG]; x3 = xp[3 * NG];
        }
#pragma unroll
        for (int k4 = 0; k4 < 32; k4++) {
            float4 w = w4[(size_t)k4 * NG];
            F4U A, B, C, D;
            A.v = *(const float4*)&h2[p][0][k4 * 4];        // rows(0,1) @ k, k+1
            B.v = *(const float4*)&h2[p][0][k4 * 4 + 2];    // rows(0,1) @ k+2, k+3
            C.v = *(const float4*)&h2[p][1][k4 * 4];        // rows(2,3) @ k, k+1
            D.v = *(const float4*)&h2[p][1][k4 * 4 + 2];
            ull2f w0 = dupf2(w.x), w1 = dupf2(w.y), w2 = dupf2(w.z), w3 = dupf2(w.w);
            acc01 = ffma2(A.u[0], w0, acc01);
            acc01 = ffma2(A.u[1], w1, acc01);
            acc01 = ffma2(B.u[0], w2, acc01);
            acc01 = ffma2(B.u[1], w3, acc01);
            acc23 = ffma2(C.u[0], w0, acc23);
            acc23 = ffma2(C.u[1], w1, acc23);
            acc23 = ffma2(D.u[0], w2, acc23);
            acc23 = ffma2(D.u[1], w3, acc23);
        }
        float r0, r1, r2, r3;
        unpackf2(acc01, r0, r1);
        unpackf2(acc23, r2, r3);

        // intra-quad gate exchange: lanes base..base+3 hold gates i,f,g,o of one asset
        const int base = lane & ~3;
        float i0 = __shfl_sync(FMASK, r0, base),     i1 = __shfl_sync(FMASK, r1, base);
        float i2 = __shfl_sync(FMASK, r2, base),     i3 = __shfl_sync(FMASK, r3, base);
        float f0 = __shfl_sync(FMASK, r0, base + 1), f1 = __shfl_sync(FMASK, r1, base + 1);
        float f2 = __shfl_sync(FMASK, r2, base + 1), f3 = __shfl_sync(FMASK, r3, base + 1);
        float g0 = __shfl_sync(FMASK, r0, base + 2), g1 = __shfl_sync(FMASK, r1, base + 2);
        float g2 = __shfl_sync(FMASK, r2, base + 2), g3 = __shfl_sync(FMASK, r3, base + 2);
        float o0 = __shfl_sync(FMASK, r0, base + 3), o1 = __shfl_sync(FMASK, r1, base + 3);
        float o2 = __shfl_sync(FMASK, r2, base + 3), o3 = __shfl_sync(FMASK, r3, base + 3);
        float vi = (kr == 0) ? i0 : (kr == 1) ? i1 : (kr == 2) ? i2 : i3;
        float vf = (kr == 0) ? f0 : (kr == 1) ? f1 : (kr == 2) ? f2 : f3;
        float vg = (kr == 0) ? g0 : (kr == 1) ? g1 : (kr == 2) ? g2 : g3;
        float vo = (kr == 0) ? o0 : (kr == 1) ? o1 : (kr == 2) ? o2 : o3;

        float cn = sigf(vf) * c_reg + sigf(vi) * tanhf(vg);
        float hn = sigf(vo) * tanhf(cn);
        c_reg = cn;
        ((float*)h2[p ^ 1])[(kr >> 1) * 256 + asset * 2 + (kr & 1)] = hn;
        g_hs[((size_t)t * NB + b0 + kr) * NH + asset] = hn;
        __syncthreads();
    }
}

// ---------------- 5) fused mean-center + cov (diag-mixed) + Q = cov@cov --------
__global__ __launch_bounds__(256) void covq_kernel() {
    extern __shared__ float sm[];
    float* covs = sm;                 // 128*132
    float* Ms = sm + 128 * 132;       // 32*132
    __shared__ float psum[256];
    __shared__ float mean_s[128];
    const int s = blockIdx.x, tid = threadIdx.x;
    const float* __restrict__ hs = g_hs + (size_t)s * NB * NH;

    {
        int col = tid & 127, part = tid >> 7;
        float a = 0.f;
        for (int l = part * 256; l < part * 256 + 256; l++) a += hs[(size_t)l * NH + col];
        psum[tid] = a;
        __syncthreads();
        if (tid < 128) mean_s[tid] = (psum[tid] + psum[tid + 128]) * (1.f / NB);
        __syncthreads();
    }

    const int tx = tid & 15, ty = tid >> 4;
    ull2f acc2[8][4];
#pragma unroll
    for (int i = 0; i < 8; i++)
#pragma unroll
        for (int j = 0; j < 4; j++) acc2[i][j] = 0ull;

    for (int l0 = 0; l0 < NB; l0 += 32) {
#pragma unroll
        for (int r = 0; r < 16; r++) {
            int li = tid + r * 256;            // [0,4096)
            int row = li >> 7, col = li & 127;
            Ms[row * 132 + col] = hs[(size_t)(l0 + row) * NH + col] - mean_s[col];
        }
        __syncthreads();
#pragma unroll
        for (int k = 0; k < 32; k++) {
            float av[8];
            *(float4*)&av[0] = *(const float4*)&Ms[k * 132 + ty * 8];
            *(float4*)&av[4] = *(const float4*)&Ms[k * 132 + ty * 8 + 4];
            F4U b0_, b1_;
            b0_.v = *(const float4*)&Ms[k * 132 + tx * 8];
            b1_.v = *(const float4*)&Ms[k * 132 + tx * 8 + 4];
            ull2f bv2[4] = { b0_.u[0], b0_.u[1], b1_.u[0], b1_.u[1] };
#pragma unroll
            for (int i = 0; i < 8; i++) {
                ull2f ad = dupf2(av[i]);
#pragma unroll
                for (int j = 0; j < 4; j++) acc2[i][j] = ffma2(ad, bv2[j], acc2[i][j]);
            }
        }
        __syncthreads();
    }

    const float inv = 1.f / (float)(NB - 1);
#pragma unroll
    for (int i = 0; i < 8; i++) {
        float a[8];
        unpackf2(acc2[i][0], a[0], a[1]);
        unpackf2(acc2[i][1], a[2], a[3]);
        unpackf2(acc2[i][2], a[4], a[5]);
        unpackf2(acc2[i][3], a[6], a[7]);
#pragma unroll
        for (int j = 0; j < 8; j++) {
            int a_ = ty * 8 + i, b_ = tx * 8 + j;
            float v = a[j] * inv;
            if (a_ != b_) v *= 0.5f;
            covs[a_ * 132 + b_] = v;
        }
    }
    __syncthreads();

    ull2f q2[8][4];
#pragma unroll
    for (int i = 0; i < 8; i++)
#pragma unroll
        for (int j = 0; j < 4; j++) q2[i][j] = 0ull;
    for (int b = 0; b < 128; b++) {
        float av[8];
        *(float4*)&av[0] = *(const float4*)&covs[b * 132 + ty * 8];
        *(float4*)&av[4] = *(const float4*)&covs[b * 132 + ty * 8 + 4];
        F4U c0_, c1_;
        c0_.v = *(const float4*)&covs[b * 132 + tx * 8];
        c1_.v = *(const float4*)&covs[b * 132 + tx * 8 + 4];
        ull2f cv2[4] = { c0_.u[0], c0_.u[1], c1_.u[0], c1_.u[1] };
#pragma unroll
        for (int i = 0; i < 8; i++) {
            ull2f ad = dupf2(av[i]);
#pragma unroll
            for (int j = 0; j < 4; j++) q2[i][j] = ffma2(ad, cv2[j], q2[i][j]);
        }
    }
    float* Qout = g_Q + (size_t)s * NH * NH;
#pragma unroll
    for (int i = 0; i < 8; i++) {
        float q[8];
        unpackf2(q2[i][0], q[0], q[1]);
        unpackf2(q2[i][1], q[2], q[3]);
        unpackf2(q2[i][2], q[4], q[5]);
        unpackf2(q2[i][3], q[6], q[7]);
#pragma unroll
        for (int j = 0; j < 8; j++)
            Qout[(size_t)(ty * 8 + i) * NH + tx * 8 + j] = q[j];
    }
}

// ---------------- 6) power iteration + FISTA, ONE warp per s -------------------
// Element mapping: lane owns elements e = lane*4 + j  (j = 0..3).
// Matvec: z broadcast via shared memory; Q rows read as coalesced LDG.128,
// accumulated with FFMA2 in 4 chains (even/odd rows) to halve dependency depth.
__device__ __forceinline__ void matvec128s(const float* __restrict__ Q, int lane,
                                           const float z[4], float y[4],
                                           float4* __restrict__ zsm) {
    zsm[lane] = make_float4(z[0], z[1], z[2], z[3]);
    __syncwarp();
    ull2f a0 = 0ull, a1 = 0ull, b0 = 0ull, b1 = 0ull;
#pragma unroll 4
    for (int m = 0; m < 32; m += 2) {
        float4 zA = zsm[m];                     // uniform address -> broadcast
        float4 zB = zsm[m + 1];
#pragma unroll
        for (int j = 0; j < 4; j++) {
            float zbA = (j == 0) ? zA.x : (j == 1) ? zA.y : (j == 2) ? zA.z : zA.w;
            float zbB = (j == 0) ? zB.x : (j == 1) ? zB.y : (j == 2) ? zB.z : zB.w;
            F4U qA, qB;
            qA.v = *(const float4*)(Q + (size_t)(m * 4 + j) * NH + lane * 4);
            qB.v = *(const float4*)(Q + (size_t)((m + 1) * 4 + j) * NH + lane * 4);
            ull2f zdA = dupf2(zbA), zdB = dupf2(zbB);
            a0 = ffma2(qA.u[0], zdA, a0);
            a1 = ffma2(qA.u[1], zdA, a1);
            b0 = ffma2(qB.u[0], zdB, b0);
            b1 = ffma2(qB.u[1], zdB, b1);
        }
    }
    __syncwarp();                               // zsm free for next overwrite
    a0 = addf2(a0, b0);
    a1 = addf2(a1, b1);
    unpackf2(a0, y[0], y[1]);
    unpackf2(a1, y[2], y[3]);
}

__global__ __launch_bounds__(32) void solve_kernel(float* __restrict__ out) {
    const int s = blockIdx.x;
    const int lane = threadIdx.x;
    const float* __restrict__ Q = g_Q + (size_t)s * NH * NH;
    __shared__ float4 zsm[32];
    const int sub = lane & 3;                   // position within quad
    const float fgrp = (float)((lane >> 2) + 1); // probe index 1..8
    const float NINTH = 1.f / 9.f;

    // power iteration for the top eigenvalue
    float bb[4];
#pragma unroll
    for (int j = 0; j < 4; j++) bb[j] = 0.08838834764831843f;   // 1/sqrt(128)
    for (int it = 0; it < 30; it++) {
        float y[4];
        matvec128s(Q, lane, bb, y, zsm);
        float nn = (y[0] * y[0] + y[1] * y[1]) + (y[2] * y[2] + y[3] * y[3]);
        nn = warpSum(nn);
        float invn = 1.f / (sqrtf(nn) + 1e-12f);
#pragma unroll
        for (int j = 0; j < 4; j++) bb[j] = y[j] * invn;
    }
    float lam;
    {
        float y[4];
        matvec128s(Q, lane, bb, y, zsm);
        float d = (bb[0] * y[0] + bb[1] * y[1]) + (bb[2] * y[2] + bb[3] * y[3]);
        lam = warpSum(d);
    }
    const float step = 1.f / (lam + 1e-8f);

    // FISTA
    float w[4], z[4];
#pragma unroll
    for (int j = 0; j < 4; j++) { w[j] = 1.f / 128.f; z[j] = w[j]; }
    float t = 1.f;
    for (int it = 0; it < 300; it++) {
        float g[4];
        matvec128s(Q, lane, z, g, zsm);
        float v[4];
#pragma unroll
        for (int j = 0; j < 4; j++) v[j] = z[j] - step * g[j];

        // replicate so each QUAD holds all 128 elements (32 per lane).
        // vr[q*4+j] = v[j] from source lane (sub + 4q); register index j is
        // loop-uniform (shuffle returns the SOURCE lane's v[j]).
        float vr[32];
#pragma unroll
        for (int q = 0; q < 8; q++)
#pragma unroll
            for (int j = 0; j < 4; j++)
                vr[q * 4 + j] = __shfl_sync(FMASK, v[j], sub + 4 * q);

        // bracket init: 4-way local trees over 32 elems, then 2-level quad reduce
        float mn, mx;
        {
            float n0 = vr[0], n1 = vr[1], n2 = vr[2], n3 = vr[3];
            float x0 = vr[0], x1 = vr[1], x2 = vr[2], x3 = vr[3];
#pragma unroll
            for (int k = 4; k < 32; k += 4) {
                n0 = fminf(n0, vr[k]);     n1 = fminf(n1, vr[k + 1]);
                n2 = fminf(n2, vr[k + 2]); n3 = fminf(n3, vr[k + 3]);
                x0 = fmaxf(x0, vr[k]);     x1 = fmaxf(x1, vr[k + 1]);
                x2 = fmaxf(x2, vr[k + 2]); x3 = fmaxf(x3, vr[k + 3]);
            }
            mn = fminf(fminf(n0, n1), fminf(n2, n3));
            mx = fmaxf(fmaxf(x0, x1), fmaxf(x2, x3));
        }
        mn = grpMin4(mn);
        mx = grpMax4(mx);
        float lo = mn - 1.f, hi = mx + 1.f;

        // 8-probe parallel interval search: 9x shrink per iter, 8 iters
        // (9^8 ~ 4.3e7 => tau0 error ~9e-8; exact refit below self-corrects)
        for (int bi = 0; bi < 8; bi++) {
            float delta = (hi - lo) * NINTH;
            float mid = fmaf(delta, fgrp, lo);
            float p0 = 0.f, p1 = 0.f, p2 = 0.f, p3 = 0.f;
#pragma unroll
            for (int k = 0; k < 32; k += 4) {
                p0 += clamp1(vr[k] - mid);
                p1 += clamp1(vr[k + 1] - mid);
                p2 += clamp1(vr[k + 2] - mid);
                p3 += clamp1(vr[k + 3] - mid);
            }
            float ss = (p0 + p1) + (p2 + p3);
            ss = grpSum4(ss);
            unsigned m = __ballot_sync(FMASK, ss > 1.f);
            int cnt = __popc(m) >> 2;               // # probes with s(mid) > 1
            float nlo = fmaf(delta, (float)cnt, lo);
            float nhi = fmaf(delta, (float)(cnt + 1), lo);
            lo = (cnt == 0) ? lo : nlo;
            hi = (cnt == 8) ? hi : nhi;
        }
        float tau0 = 0.5f * (lo + hi);

        // exact active-set refit (same classification as reference);
        // 4-way local accumulators + 2-level quad reduce per quantity
        float cs0 = 0.f, cs1 = 0.f, cs2 = 0.f, cs3 = 0.f;
        float vs0 = 0.f, vs1 = 0.f, vs2 = 0.f, vs3 = 0.f;
        float bs0 = 0.f, bs1 = 0.f, bs2 = 0.f, bs3 = 0.f;
#pragma unroll
        for (int k = 0; k < 32; k += 4) {
#pragma unroll
            for (int j = 0; j < 4; j++) {
                float w0 = clamp1(vr[k + j] - tau0);
                bool inter = fabsf(w0) < 1.f - 1e-6f;
                float ci = inter ? 1.f : 0.f;
                float vi = inter ? vr[k + j] : 0.f;
                float bi_ = inter ? 0.f : w0;
                if (j == 0)      { cs0 += ci; vs0 += vi; bs0 += bi_; }
                else if (j == 1) { cs1 += ci; vs1 += vi; bs1 += bi_; }
                else if (j == 2) { cs2 += ci; vs2 += vi; bs2 += bi_; }
                else             { cs3 += ci; vs3 += vi; bs3 += bi_; }
            }
        }
        float cs = (cs0 + cs1) + (cs2 + cs3);
        float vs = (vs0 + vs1) + (vs2 + vs3);
        float bs = (bs0 + bs1) + (bs2 + bs3);
        cs = grpSum4(cs);
        vs = grpSum4(vs);
        bs = grpSum4(bs);
        float tau = (vs - (1.f - bs)) / fmaxf(cs, 1.f);
        float wn[4];
#pragma unroll
        for (int j = 0; j < 4; j++) wn[j] = clamp1(v[j] - tau);

        float tn = 0.5f * (1.f + sqrtf(1.f + 4.f * t * t));
        float coef = (t - 1.f) / tn;
#pragma unroll
        for (int j = 0; j < 4; j++) {
            z[j] = wn[j] + coef * (wn[j] - w[j]);
            w[j] = wn[j];
        }
        t = tn;
    }
#pragma unroll
    for (int j = 0; j < 4; j++)
        out[(size_t)s * NH + lane * 4 + j] = w[j];
}

// ---------------- launch: single stream --------------------------------------
extern "C" void kernel_launch(void* const* d_in, const int* in_sizes, int n_in,
                              void* d_out, int out_size) {
    const float* x    = (const float*)d_in[0];
    const float* in_w = (const float*)d_in[1];
    const float* in_b = (const float*)d_in[2];
    const float* W_ih = (const float*)d_in[3];
    const float* W_hh = (const float*)d_in[4];
    const float* b_ih = (const float*)d_in[5];
    const float* b_hh = (const float*)d_in[6];
    float* out = (float*)d_out;

    init_kernel<<<512, 256>>>(x, W_ih, W_hh, b_ih, b_hh);
    xg_gemm_kernel<<<dim3(1024, 4), 256>>>(x, in_w, in_b);
    lstm_kernel<<<NB / 4, 512>>>();

    const int covq_smem = (128 * 132 + 32 * 132) * (int)sizeof(float);  // 84480 B
    cudaFuncSetAttribute(covq_kernel, cudaFuncAttributeMaxDynamicSharedMemorySize, covq_smem);
    covq_kernel<<<NS, 256, covq_smem>>>();

    solve_kernel<<<NS, 32>>>(out);
}

// round 16
// speedup vs baseline: 1.0668x; 1.0668x over previous
#include <cuda_runtime.h>
#include <math.h>

#define NS 256   // time steps (s axis of output)
#define NB 512   // batch rows (l axis)
#define NH 128   // hidden / asset dim
#define NG 512   // 4*H gates

// ---------------- static device scratch (no allocations allowed) ----------------
__device__ float g_mean[NS];
__device__ float g_istd[NS];
__device__ float g_rowsumW[NG];                   // permuted column index
__device__ float g_bihP[NG];                      // permuted b_ih
__device__ float g_bhhP[NG];                      // permuted b_hh
__device__ float g_WihT[NH * NG];                 // [k][c]  (c = 4*asset+gate)
__device__ float g_Whh4[NH * NG];                 // [k>>2][c][k&3]  (float4-packed)
__device__ float g_xg[(size_t)NS * NB * NG];      // [t][b][c]
__device__ float g_hs[(size_t)NS * NB * NH];      // [t][b][a]
__device__ float g_Q[(size_t)NS * NH * NH];       // [s][a][c]

__device__ __forceinline__ float sigf(float x) { return 1.f / (1.f + expf(-x)); }
__device__ __forceinline__ float clamp1(float x) { return fminf(1.f, fmaxf(-1.f, x)); }

#define FMASK 0xffffffffu

__device__ __forceinline__ float warpSum(float v) {
#pragma unroll
    for (int o = 16; o > 0; o >>= 1) v += __shfl_xor_sync(FMASK, v, o);
    return v;
}
// 8-lane group reductions (xor offsets 1,2,4 stay within each 8-lane group)
__device__ __forceinline__ float grpSum8(float v) {
    v += __shfl_xor_sync(FMASK, v, 1);
    v += __shfl_xor_sync(FMASK, v, 2);
    v += __shfl_xor_sync(FMASK, v, 4);
    return v;
}
__device__ __forceinline__ float grpMin8(float v) {
    v = fminf(v, __shfl_xor_sync(FMASK, v, 1));
    v = fminf(v, __shfl_xor_sync(FMASK, v, 2));
    v = fminf(v, __shfl_xor_sync(FMASK, v, 4));
    return v;
}
__device__ __forceinline__ float grpMax8(float v) {
    v = fmaxf(v, __shfl_xor_sync(FMASK, v, 1));
    v = fmaxf(v, __shfl_xor_sync(FMASK, v, 2));
    v = fmaxf(v, __shfl_xor_sync(FMASK, v, 4));
    return v;
}

// ---- packed f32x2 helpers (Blackwell FFMA2: 2 IEEE FMAs per instruction) ----
typedef unsigned long long ull2f;
union F4U { float4 v; ull2f u[2]; };

__device__ __forceinline__ ull2f ffma2(ull2f a, ull2f b, ull2f c) {
    ull2f d;
    asm("fma.rn.f32x2 %0, %1, %2, %3;" : "=l"(d) : "l"(a), "l"(b), "l"(c));
    return d;
}
__device__ __forceinline__ ull2f packf2(float lo, float hi) {
    ull2f o;
    asm("mov.b64 %0, {%1, %2};" : "=l"(o) : "f"(lo), "f"(hi));
    return o;
}
__device__ __forceinline__ ull2f dupf2(float x) {
    ull2f o;
    asm("mov.b64 %0, {%1, %1};" : "=l"(o) : "f"(x));
    return o;
}
__device__ __forceinline__ void unpackf2(ull2f p, float& lo, float& hi) {
    asm("mov.b64 {%0, %1}, %2;" : "=f"(lo), "=f"(hi) : "l"(p));
}

// ---------------- 1+2) fused: moments (blocks 0..255) + prep (blocks 256..511) --
// stored column c = 4*asset + gate   (orig column g = gate*128 + asset)
__global__ __launch_bounds__(256) void init_kernel(const float* __restrict__ x,
                                                   const float* __restrict__ Wih,
                                                   const float* __restrict__ Whh,
                                                   const float* __restrict__ b_ih,
                                                   const float* __restrict__ b_hh) {
    if (blockIdx.x < NS) {
        const int s = blockIdx.x;
        const float* xs = x + (size_t)s * (NB * NH);
        float sum = 0.f, sq = 0.f;
        for (int i = threadIdx.x; i < NB * NH; i += 256) {
            float v = xs[i];
            sum += v; sq += v * v;
        }
        __shared__ float s1[256], s2[256];
        s1[threadIdx.x] = sum; s2[threadIdx.x] = sq;
        __syncthreads();
        for (int o = 128; o > 0; o >>= 1) {
            if (threadIdx.x < o) {
                s1[threadIdx.x] += s1[threadIdx.x + o];
                s2[threadIdx.x] += s2[threadIdx.x + o];
            }
            __syncthreads();
        }
        if (threadIdx.x == 0) {
            const float invn = 1.f / (float)(NB * NH);
            float mean = s1[0] * invn;
            float var = s2[0] * invn - mean * mean;
            g_mean[s] = mean;
            g_istd[s] = 1.f / sqrtf(var + 1e-5f);
        }
    } else {
        int idx = (blockIdx.x - NS) * 256 + threadIdx.x;   // [0, 65536)
        int g = idx >> 7, k = idx & 127;
        int c = 4 * (g & 127) + (g >> 7);
        g_WihT[k * NG + c] = Wih[(size_t)g * NH + k];
        g_Whh4[(k >> 2) * (NG * 4) + c * 4 + (k & 3)] = Whh[(size_t)g * NH + k];
        if (idx < NG) {
            float s = 0.f;
            for (int kk = 0; kk < NH; kk++) s += Wih[(size_t)idx * NH + kk];
            int cc = 4 * (idx & 127) + (idx >> 7);
            g_rowsumW[cc] = s;
            g_bihP[cc] = b_ih[idx];
            g_bhhP[cc] = b_hh[idx];
        }
    }
}

// ---------------- 3) xg = IN(x) @ WihT + b_ih (IN folded into epilogue) --------
// 128x128 tile, 8x8 micro-tile via f32x2 packed FMA, k-step 16, 2 CTAs/SM.
__global__ __launch_bounds__(256, 2) void xg_gemm_kernel(const float* __restrict__ x,
                                                         const float* __restrict__ in_w,
                                                         const float* __restrict__ in_b) {
    __shared__ float As[16][132];   // [k][m]
    __shared__ float Bs[16][132];   // [k][c]
    const int m0 = blockIdx.x * 128;
    const int g0 = blockIdx.y * 128;
    const int tid = threadIdx.x;
    const int tx = tid & 15, ty = tid >> 4;
    ull2f acc2[8][4];
#pragma unroll
    for (int i = 0; i < 8; i++)
#pragma unroll
        for (int j = 0; j < 4; j++) acc2[i][j] = 0ull;   // (0.f, 0.f)

    for (int k0 = 0; k0 < 128; k0 += 16) {
#pragma unroll
        for (int r = 0; r < 2; r++) {
            int li = tid + r * 256;            // [0,512): A = 128 rows x 16 k
            int row = li >> 2, c4 = li & 3;
            float4 v = *(const float4*)(x + (size_t)(m0 + row) * NH + k0 + c4 * 4);
            As[c4 * 4 + 0][row] = v.x;
            As[c4 * 4 + 1][row] = v.y;
            As[c4 * 4 + 2][row] = v.z;
            As[c4 * 4 + 3][row] = v.w;
        }
#pragma unroll
        for (int r = 0; r < 2; r++) {
            int li = tid + r * 256;            // [0,512): B = 16 k x 128 c
            int kk = li >> 5, g4 = li & 31;
            float4 v = *(const float4*)(g_WihT + (size_t)(k0 + kk) * NG + g0 + g4 * 4);
            *(float4*)&Bs[kk][g4 * 4] = v;
        }
        __syncthreads();
#pragma unroll
        for (int k = 0; k < 16; k++) {
            float av[8];
            *(float4*)&av[0] = *(const float4*)&As[k][ty * 8];
            *(float4*)&av[4] = *(const float4*)&As[k][ty * 8 + 4];
            F4U b0_, b1_;
            b0_.v = *(const float4*)&Bs[k][tx * 4];
            b1_.v = *(const float4*)&Bs[k][64 + tx * 4];
            ull2f bv2[4] = { b0_.u[0], b0_.u[1], b1_.u[0], b1_.u[1] };
#pragma unroll
            for (int i = 0; i < 8; i++) {
                ull2f ad = dupf2(av[i]);
#pragma unroll
                for (int j = 0; j < 4; j++) acc2[i][j] = ffma2(ad, bv2[j], acc2[i][j]);
            }
        }
        __syncthreads();
    }
    const int s = m0 >> 9;                      // 512 rows per time step
    const float iw = in_w[0], ib = in_b[0];
    const float alpha = iw * g_istd[s];
    const float gamma = ib - alpha * g_mean[s];
    float base[8];
#pragma unroll
    for (int j = 0; j < 8; j++) {
        int gi = (j < 4) ? (g0 + tx * 4 + j) : (g0 + 64 + tx * 4 + (j - 4));
        base[j] = gamma * g_rowsumW[gi] + g_bihP[gi];
    }
#pragma unroll
    for (int i = 0; i < 8; i++) {
        int m = m0 + ty * 8 + i;
        float a0, a1, a2, a3, a4, a5, a6, a7;
        unpackf2(acc2[i][0], a0, a1);
        unpackf2(acc2[i][1], a2, a3);
        unpackf2(acc2[i][2], a4, a5);
        unpackf2(acc2[i][3], a6, a7);
        float4 o0, o1;
        o0.x = fmaf(alpha, a0, base[0]);
        o0.y = fmaf(alpha, a1, base[1]);
        o0.z = fmaf(alpha, a2, base[2]);
        o0.w = fmaf(alpha, a3, base[3]);
        o1.x = fmaf(alpha, a4, base[4]);
        o1.y = fmaf(alpha, a5, base[5]);
        o1.z = fmaf(alpha, a6, base[6]);
        o1.w = fmaf(alpha, a7, base[7]);
        *(float4*)(g_xg + (size_t)m * NG + g0 + tx * 4) = o0;
        *(float4*)(g_xg + (size_t)m * NG + g0 + 64 + tx * 4) = o1;
    }
}

// ---------------- 4) LSTM: 4 rows/CTA, gate-interleaved, xg prefetch -----------
__global__ __launch_bounds__(512) void lstm_kernel() {
    const int b0 = blockIdx.x * 4;
    const int c = threadIdx.x;                 // permuted column 0..511
    const int lane = c & 31;
    const int kr = lane & 3;                   // row this lane activates
    const int asset = c >> 2;                  // asset this lane activates
    __shared__ float2 h2[2][2][128];           // [buf][rowpair][k]
    ((float*)h2[0])[(kr >> 1) * 256 + asset * 2 + (kr & 1)] = 0.f;
    float c_reg = 0.f;
    const float bhh = g_bhhP[c];
    const float4* __restrict__ w4 = ((const float4*)g_Whh4) + c;   // row k4: +k4*NG
    __syncthreads();

    // prefetch xg for t = 0
    float x0, x1, x2, x3;
    {
        const float* xp = g_xg + (size_t)b0 * NG + c;
        x0 = xp[0]; x1 = xp[NG]; x2 = xp[2 * NG]; x3 = xp[3 * NG];
    }

    for (int t = 0; t < NS; t++) {
        const int p = t & 1;
        ull2f acc01 = packf2(x0 + bhh, x1 + bhh);
        ull2f acc23 = packf2(x2 + bhh, x3 + bhh);
        // issue next step's xg loads now; consumed after the barrier
        {
            int tn = (t + 1 < NS) ? t + 1 : t;
            const float* xp = g_xg + ((size_t)tn * NB + b0) * NG + c;
            x0 = xp[0]; x1 = xp[NG]; x2 = xp[2 * NG]; x3 = xp[3 * NG];
        }
#pragma unroll
        for (int k4 = 0; k4 < 32; k4++) {
            float4 w = w4[(size_t)k4 * NG];
            F4U A, B, C, D;
            A.v = *(const float4*)&h2[p][0][k4 * 4];        // rows(0,1) @ k, k+1
            B.v = *(const float4*)&h2[p][0][k4 * 4 + 2];    // rows(0,1) @ k+2, k+3
            C.v = *(const float4*)&h2[p][1][k4 * 4];        // rows(2,3) @ k, k+1
            D.v = *(const float4*)&h2[p][1][k4 * 4 + 2];
            ull2f w0 = dupf2(w.x), w1 = dupf2(w.y), w2 = dupf2(w.z), w3 = dupf2(w.w);
            acc01 = ffma2(A.u[0], w0, acc01);
            acc01 = ffma2(A.u[1], w1, acc01);
            acc01 = ffma2(B.u[0], w2, acc01);
            acc01 = ffma2(B.u[1], w3, acc01);
            acc23 = ffma2(C.u[0], w0, acc23);
            acc23 = ffma2(C.u[1], w1, acc23);
            acc23 = ffma2(D.u[0], w2, acc23);
            acc23 = ffma2(D.u[1], w3, acc23);
        }
        float r0, r1, r2, r3;
        unpackf2(acc01, r0, r1);
        unpackf2(acc23, r2, r3);

        // intra-quad gate exchange: lanes base..base+3 hold gates i,f,g,o of one asset
        const int base = lane & ~3;
        float i0 = __shfl_sync(FMASK, r0, base),     i1 = __shfl_sync(FMASK, r1, base);
        float i2 = __shfl_sync(FMASK, r2, base),     i3 = __shfl_sync(FMASK, r3, base);
        float f0 = __shfl_sync(FMASK, r0, base + 1), f1 = __shfl_sync(FMASK, r1, base + 1);
        float f2 = __shfl_sync(FMASK, r2, base + 1), f3 = __shfl_sync(FMASK, r3, base + 1);
        float g0 = __shfl_sync(FMASK, r0, base + 2), g1 = __shfl_sync(FMASK, r1, base + 2);
        float g2 = __shfl_sync(FMASK, r2, base + 2), g3 = __shfl_sync(FMASK, r3, base + 2);
        float o0 = __shfl_sync(FMASK, r0, base + 3), o1 = __shfl_sync(FMASK, r1, base + 3);
        float o2 = __shfl_sync(FMASK, r2, base + 3), o3 = __shfl_sync(FMASK, r3, base + 3);
        float vi = (kr == 0) ? i0 : (kr == 1) ? i1 : (kr == 2) ? i2 : i3;
        float vf = (kr == 0) ? f0 : (kr == 1) ? f1 : (kr == 2) ? f2 : f3;
        float vg = (kr == 0) ? g0 : (kr == 1) ? g1 : (kr == 2) ? g2 : g3;
        float vo = (kr == 0) ? o0 : (kr == 1) ? o1 : (kr == 2) ? o2 : o3;

        float cn = sigf(vf) * c_reg + sigf(vi) * tanhf(vg);
        float hn = sigf(vo) * tanhf(cn);
        c_reg = cn;
        ((float*)h2[p ^ 1])[(kr >> 1) * 256 + asset * 2 + (kr & 1)] = hn;
        g_hs[((size_t)t * NB + b0 + kr) * NH + asset] = hn;
        __syncthreads();
    }
}

// ---------------- 5) fused mean-center + cov (diag-mixed) + Q = cov@cov --------
// Both GEMM loops use packed FFMA2; regs capped for 2 CTAs/SM.
__global__ __launch_bounds__(256, 2) void covq_kernel() {
    extern __shared__ float sm[];
    float* covs = sm;                 // 128*132
    float* Ms = sm + 128 * 132;       // 32*132
    __shared__ float psum[256];
    __shared__ float mean_s[128];
    const int s = blockIdx.x, tid = threadIdx.x;
    const float* __restrict__ hs = g_hs + (size_t)s * NB * NH;

    {
        int col = tid & 127, part = tid >> 7;
        float a = 0.f;
        for (int l = part * 256; l < part * 256 + 256; l++) a += hs[(size_t)l * NH + col];
        psum[tid] = a;
        __syncthreads();
        if (tid < 128) mean_s[tid] = (psum[tid] + psum[tid + 128]) * (1.f / NB);
        __syncthreads();
    }

    const int tx = tid & 15, ty = tid >> 4;
    ull2f acc2[8][4];
#pragma unroll
    for (int i = 0; i < 8; i++)
#pragma unroll
        for (int j = 0; j < 4; j++) acc2[i][j] = 0ull;

    for (int l0 = 0; l0 < NB; l0 += 32) {
#pragma unroll
        for (int r = 0; r < 16; r++) {
            int li = tid + r * 256;            // [0,4096)
            int row = li >> 7, col = li & 127;
            Ms[row * 132 + col] = hs[(size_t)(l0 + row) * NH + col] - mean_s[col];
        }
        __syncthreads();
#pragma unroll
        for (int k = 0; k < 32; k++) {
            float av[8];
            *(float4*)&av[0] = *(const float4*)&Ms[k * 132 + ty * 8];
            *(float4*)&av[4] = *(const float4*)&Ms[k * 132 + ty * 8 + 4];
            F4U b0_, b1_;
            b0_.v = *(const float4*)&Ms[k * 132 + tx * 8];
            b1_.v = *(const float4*)&Ms[k * 132 + tx * 8 + 4];
            ull2f bv2[4] = { b0_.u[0], b0_.u[1], b1_.u[0], b1_.u[1] };
#pragma unroll
            for (int i = 0; i < 8; i++) {
                ull2f ad = dupf2(av[i]);
#pragma unroll
                for (int j = 0; j < 4; j++) acc2[i][j] = ffma2(ad, bv2[j], acc2[i][j]);
            }
        }
        __syncthreads();
    }

    const float inv = 1.f / (float)(NB - 1);
#pragma unroll
    for (int i = 0; i < 8; i++) {
        float a[8];
        unpackf2(acc2[i][0], a[0], a[1]);
        unpackf2(acc2[i][1], a[2], a[3]);
        unpackf2(acc2[i][2], a[4], a[5]);
        unpackf2(acc2[i][3], a[6], a[7]);
#pragma unroll
        for (int j = 0; j < 8; j++) {
            int a_ = ty * 8 + i, b_ = tx * 8 + j;
            float v = a[j] * inv;
            if (a_ != b_) v *= 0.5f;
            covs[a_ * 132 + b_] = v;
        }
    }
    __syncthreads();

    ull2f q2[8][4];
#pragma unroll
    for (int i = 0; i < 8; i++)
#pragma unroll
        for (int j = 0; j < 4; j++) q2[i][j] = 0ull;
    for (int b = 0; b < 128; b++) {
        float av[8];
        *(float4*)&av[0] = *(const float4*)&covs[b * 132 + ty * 8];
        *(float4*)&av[4] = *(const float4*)&covs[b * 132 + ty * 8 + 4];
        F4U c0_, c1_;
        c0_.v = *(const float4*)&covs[b * 132 + tx * 8];
        c1_.v = *(const float4*)&covs[b * 132 + tx * 8 + 4];
        ull2f cv2[4] = { c0_.u[0], c0_.u[1], c1_.u[0], c1_.u[1] };
#pragma unroll
        for (int i = 0; i < 8; i++) {
            ull2f ad = dupf2(av[i]);
#pragma unroll
            for (int j = 0; j < 4; j++) q2[i][j] = ffma2(ad, cv2[j], q2[i][j]);
        }
    }
    float* Qout = g_Q + (size_t)s * NH * NH;
#pragma unroll
    for (int i = 0; i < 8; i++) {
        float q[8];
        unpackf2(q2[i][0], q[0], q[1]);
        unpackf2(q2[i][1], q[2], q[3]);
        unpackf2(q2[i][2], q[4], q[5]);
        unpackf2(q2[i][3], q[6], q[7]);
#pragma unroll
        for (int j = 0; j < 8; j++)
            Qout[(size_t)(ty * 8 + i) * NH + tx * 8 + j] = q[j];
    }
}

// ---------------- 6) power iteration + FISTA, ONE warp per s -------------------
// Element mapping: lane owns elements e = lane*4 + j  (j = 0..3).
// Matvec: z broadcast via shared memory (1 STS.128 + 32 uniform LDS.128); Q rows
// read as coalesced LDG.128, accumulated with FFMA2.
__device__ __forceinline__ void matvec128s(const float* __restrict__ Q, int lane,
                                           const float z[4], float y[4],
                                           float4* __restrict__ zsm) {
    zsm[lane] = make_float4(z[0], z[1], z[2], z[3]);
    __syncwarp();
    ull2f a0 = 0ull, a1 = 0ull;
#pragma unroll 8
    for (int m = 0; m < 32; m++) {
        float4 zz = zsm[m];                     // uniform address -> broadcast
#pragma unroll
        for (int j = 0; j < 4; j++) {
            float zb = (j == 0) ? zz.x : (j == 1) ? zz.y : (j == 2) ? zz.z : zz.w;
            F4U q;
            q.v = *(const float4*)(Q + (size_t)(m * 4 + j) * NH + lane * 4);
            ull2f zd = dupf2(zb);
            a0 = ffma2(q.u[0], zd, a0);
            a1 = ffma2(q.u[1], zd, a1);
        }
    }
    __syncwarp();                               // zsm free for next overwrite
    unpackf2(a0, y[0], y[1]);
    unpackf2(a1, y[2], y[3]);
}

__global__ __launch_bounds__(32) void solve_kernel(float* __restrict__ out) {
    const int s = blockIdx.x;
    const int lane = threadIdx.x;
    const float* __restrict__ Q = g_Q + (size_t)s * NH * NH;
    __shared__ float4 zsm[32];
    const int sub = lane & 7;
    const float fgrp = (float)((lane >> 3) + 1);

    // power iteration for the top eigenvalue
    float bb[4];
#pragma unroll
    for (int j = 0; j < 4; j++) bb[j] = 0.08838834764831843f;   // 1/sqrt(128)
    for (int it = 0; it < 30; it++) {
        float y[4];
        matvec128s(Q, lane, bb, y, zsm);
        float nn = (y[0] * y[0] + y[1] * y[1]) + (y[2] * y[2] + y[3] * y[3]);
        nn = warpSum(nn);
        float invn = 1.f / (sqrtf(nn) + 1e-12f);
#pragma unroll
        for (int j = 0; j < 4; j++) bb[j] = y[j] * invn;
    }
    float lam;
    {
        float y[4];
        matvec128s(Q, lane, bb, y, zsm);
        float d = (bb[0] * y[0] + bb[1] * y[1]) + (bb[2] * y[2] + bb[3] * y[3]);
        lam = warpSum(d);
    }
    const float step = 1.f / (lam + 1e-8f);

    // FISTA with warm-started projection bracket.
    // tau is 1-Lipschitz in v: tau*(v+d) in [tau*(v)+min d, tau*(v)+max d]
    // (clip is monotone). vrp = previous vr; tau_prev = its exact dual.
    // Init: vrp = 1/128 uniform => tau_prev = 0 exactly.
    float w[4], z[4];
#pragma unroll
    for (int j = 0; j < 4; j++) { w[j] = 1.f / 128.f; z[j] = w[j]; }
    float vrp[16];
#pragma unroll
    for (int k = 0; k < 16; k++) vrp[k] = 1.f / 128.f;
    float tau_prev = 0.f;
    float t = 1.f;
    for (int it = 0; it < 300; it++) {
        float g[4];
        matvec128s(Q, lane, z, g, zsm);
        float v[4];
#pragma unroll
        for (int j = 0; j < 4; j++) v[j] = z[j] - step * g[j];

        // replicate so each 8-lane group holds all 128 elements.
        // vr[q*4+j] = v[j] from source lane (sub + 8q); register index j is
        // loop-uniform (shuffle returns the SOURCE lane's v[j]).
        float vr[16];
#pragma unroll
        for (int q = 0; q < 4; q++)
#pragma unroll
            for (int j = 0; j < 4; j++)
                vr[q * 4 + j] = __shfl_sync(FMASK, v[j], sub + 8 * q);

        // warm bracket: min/max of (vr - vrp), pairwise tree + group reduce
        float mnD, mxD;
        {
            float d_[16];
#pragma unroll
            for (int k = 0; k < 16; k++) d_[k] = vr[k] - vrp[k];
            float m0 = fminf(d_[0], d_[1]),  m1 = fminf(d_[2], d_[3]);
            float m2 = fminf(d_[4], d_[5]),  m3 = fminf(d_[6], d_[7]);
            float m4 = fminf(d_[8], d_[9]),  m5 = fminf(d_[10], d_[11]);
            float m6 = fminf(d_[12], d_[13]), m7 = fminf(d_[14], d_[15]);
            mnD = fminf(fminf(fminf(m0, m1), fminf(m2, m3)),
                        fminf(fminf(m4, m5), fminf(m6, m7)));
            float x0 = fmaxf(d_[0], d_[1]),  x1 = fmaxf(d_[2], d_[3]);
            float x2 = fmaxf(d_[4], d_[5]),  x3 = fmaxf(d_[6], d_[7]);
            float x4 = fmaxf(d_[8], d_[9]),  x5 = fmaxf(d_[10], d_[11]);
            float x6 = fmaxf(d_[12], d_[13]), x7 = fmaxf(d_[14], d_[15]);
            mxD = fmaxf(fmaxf(fmaxf(x0, x1), fmaxf(x2, x3)),
                        fmaxf(fmaxf(x4, x5), fmaxf(x6, x7)));
        }
        mnD = grpMin8(mnD);
        mxD = grpMax8(mxD);
        float lo = tau_prev + mnD - 1e-3f;
        float hi = tau_prev + mxD + 1e-3f;

        // 4-probe parallel interval search: 5x shrink per iter, 7 iters.
        // Typical warm width ~1e-2 => tau0 error ~1e-7; worst-case early
        // width ~1 => ~1.3e-5, absorbed by the exact refit below.
        for (int bi = 0; bi < 7; bi++) {
            float delta = 0.2f * (hi - lo);
            float mid = fmaf(delta, fgrp, lo);
            float c0 = clamp1(vr[0] - mid) + clamp1(vr[1] - mid);
            float c1 = clamp1(vr[2] - mid) + clamp1(vr[3] - mid);
            float c2 = clamp1(vr[4] - mid) + clamp1(vr[5] - mid);
            float c3 = clamp1(vr[6] - mid) + clamp1(vr[7] - mid);
            float c4 = clamp1(vr[8] - mid) + clamp1(vr[9] - mid);
            float c5 = clamp1(vr[10] - mid) + clamp1(vr[11] - mid);
            float c6 = clamp1(vr[12] - mid) + clamp1(vr[13] - mid);
            float c7 = clamp1(vr[14] - mid) + clamp1(vr[15] - mid);
            float ss = ((c0 + c1) + (c2 + c3)) + ((c4 + c5) + (c6 + c7));
            ss = grpSum8(ss);
            unsigned m = __ballot_sync(FMASK, ss > 1.f);
            int cnt = __popc(m) >> 3;               // # probes with s(mid) > 1
            float nlo = fmaf(delta, (float)cnt, lo);
            float nhi = fmaf(delta, (float)(cnt + 1), lo);
            lo = (cnt == 0) ? lo : nlo;
            hi = (cnt == 4) ? hi : nhi;
        }
        float tau0 = 0.5f * (lo + hi);

        // exact active-set refit (same classification as reference);
        // pairwise-tree local sums + 3-level group reduce per quantity
        float csl[16], vsl[16], bsl[16];
#pragma unroll
        for (int k = 0; k < 16; k++) {
            float w0 = clamp1(vr[k] - tau0);
            bool inter = fabsf(w0) < 1.f - 1e-6f;
            csl[k] = inter ? 1.f : 0.f;
            vsl[k] = inter ? vr[k] : 0.f;
            bsl[k] = inter ? 0.f : w0;
        }
        float cs, vs, bs;
        {
            float a0 = (csl[0] + csl[1]) + (csl[2] + csl[3]);
            float a1 = (csl[4] + csl[5]) + (csl[6] + csl[7]);
            float a2 = (csl[8] + csl[9]) + (csl[10] + csl[11]);
            float a3 = (csl[12] + csl[13]) + (csl[14] + csl[15]);
            cs = (a0 + a1) + (a2 + a3);
            float b0 = (vsl[0] + vsl[1]) + (vsl[2] + vsl[3]);
            float b1 = (vsl[4] + vsl[5]) + (vsl[6] + vsl[7]);
            float b2 = (vsl[8] + vsl[9]) + (vsl[10] + vsl[11]);
            float b3 = (vsl[12] + vsl[13]) + (vsl[14] + vsl[15]);
            vs = (b0 + b1) + (b2 + b3);
            float d0 = (bsl[0] + bsl[1]) + (bsl[2] + bsl[3]);
            float d1 = (bsl[4] + bsl[5]) + (bsl[6] + bsl[7]);
            float d2 = (bsl[8] + bsl[9]) + (bsl[10] + bsl[11]);
            float d3 = (bsl[12] + bsl[13]) + (bsl[14] + bsl[15]);
            bs = (d0 + d1) + (d2 + d3);
        }
        cs = grpSum8(cs);
        vs = grpSum8(vs);
        bs = grpSum8(bs);
        float tau = (vs - (1.f - bs)) / fmaxf(cs, 1.f);
        float wn[4];
#pragma unroll
        for (int j = 0; j < 4; j++) wn[j] = clamp1(v[j] - tau);

        // save warm-start state
#pragma unroll
        for (int k = 0; k < 16; k++) vrp[k] = vr[k];
        tau_prev = tau;

        float tn = 0.5f * (1.f + sqrtf(1.f + 4.f * t * t));
        float coef = (t - 1.f) / tn;
#pragma unroll
        for (int j = 0; j < 4; j++) {
            z[j] = wn[j] + coef * (wn[j] - w[j]);
            w[j] = wn[j];
        }
        t = tn;
    }
#pragma unroll
    for (int j = 0; j < 4; j++)
        out[(size_t)s * NH + lane * 4 + j] = w[j];
}

// ---------------- launch: single stream --------------------------------------
extern "C" void kernel_launch(void* const* d_in, const int* in_sizes, int n_in,
                              void* d_out, int out_size) {
    const float* x    = (const float*)d_in[0];
    const float* in_w = (const float*)d_in[1];
    const float* in_b = (const float*)d_in[2];
    const float* W_ih = (const float*)d_in[3];
    const float* W_hh = (const float*)d_in[4];
    const float* b_ih = (const float*)d_in[5];
    const float* b_hh = (const float*)d_in[6];
    float* out = (float*)d_out;

    init_kernel<<<512, 256>>>(x, W_ih, W_hh, b_ih, b_hh);
    xg_gemm_kernel<<<dim3(1024, 4), 256>>>(x, in_w, in_b);
    lstm_kernel<<<NB / 4, 512>>>();

    const int covq_smem = (128 * 132 + 32 * 132) * (int)sizeof(float);  // 84480 B
    cudaFuncSetAttribute(covq_kernel, cudaFuncAttributeMaxDynamicSharedMemorySize, covq_smem);
    covq_kernel<<<NS, 256, covq_smem>>>();

    solve_kernel<<<NS, 32>>>(out);
}

// round 17
// speedup vs baseline: 1.0967x; 1.0280x over previous
#include <cuda_runtime.h>
#include <math.h>

#define NS 256   // time steps (s axis of output)
#define NB 512   // batch rows (l axis)
#define NH 128   // hidden / asset dim
#define NG 512   // 4*H gates

// ---------------- static device scratch (no allocations allowed) ----------------
__device__ float g_mean[NS];
__device__ float g_istd[NS];
__device__ float g_rowsumW[NG];                   // permuted column index
__device__ float g_bihP[NG];                      // permuted b_ih
__device__ float g_bhhP[NG];                      // permuted b_hh
__device__ float g_WihT[NH * NG];                 // [k][c]  (c = 4*asset+gate)
__device__ float g_Whh4[NH * NG];                 // [k>>2][c][k&3]  (float4-packed)
__device__ float g_xg[(size_t)NS * NB * NG];      // [t][b][c]
__device__ float g_hs[(size_t)NS * NB * NH];      // [t][b][a]
__device__ float g_Q[(size_t)NS * NH * NH];       // [s][a][c]

__device__ __forceinline__ float sigf(float x) { return 1.f / (1.f + expf(-x)); }
__device__ __forceinline__ float clamp1(float x) { return fminf(1.f, fmaxf(-1.f, x)); }

#define FMASK 0xffffffffu

__device__ __forceinline__ float warpSum(float v) {
#pragma unroll
    for (int o = 16; o > 0; o >>= 1) v += __shfl_xor_sync(FMASK, v, o);
    return v;
}
// 8-lane group reductions (xor offsets 1,2,4 stay within each 8-lane group)
__device__ __forceinline__ float grpSum8(float v) {
    v += __shfl_xor_sync(FMASK, v, 1);
    v += __shfl_xor_sync(FMASK, v, 2);
    v += __shfl_xor_sync(FMASK, v, 4);
    return v;
}
__device__ __forceinline__ float grpMin8(float v) {
    v = fminf(v, __shfl_xor_sync(FMASK, v, 1));
    v = fminf(v, __shfl_xor_sync(FMASK, v, 2));
    v = fminf(v, __shfl_xor_sync(FMASK, v, 4));
    return v;
}
__device__ __forceinline__ float grpMax8(float v) {
    v = fmaxf(v, __shfl_xor_sync(FMASK, v, 1));
    v = fmaxf(v, __shfl_xor_sync(FMASK, v, 2));
    v = fmaxf(v, __shfl_xor_sync(FMASK, v, 4));
    return v;
}

// ---- packed f32x2 helpers (Blackwell FFMA2: 2 IEEE FMAs per instruction) ----
typedef unsigned long long ull2f;
union F4U { float4 v; ull2f u[2]; };

__device__ __forceinline__ ull2f ffma2(ull2f a, ull2f b, ull2f c) {
    ull2f d;
    asm("fma.rn.f32x2 %0, %1, %2, %3;" : "=l"(d) : "l"(a), "l"(b), "l"(c));
    return d;
}
__device__ __forceinline__ ull2f packf2(float lo, float hi) {
    ull2f o;
    asm("mov.b64 %0, {%1, %2};" : "=l"(o) : "f"(lo), "f"(hi));
    return o;
}
__device__ __forceinline__ ull2f dupf2(float x) {
    ull2f o;
    asm("mov.b64 %0, {%1, %1};" : "=l"(o) : "f"(x));
    return o;
}
__device__ __forceinline__ void unpackf2(ull2f p, float& lo, float& hi) {
    asm("mov.b64 {%0, %1}, %2;" : "=f"(lo), "=f"(hi) : "l"(p));
}

// ---------------- 1+2) fused: moments (blocks 0..255) + prep (blocks 256..511) --
// stored column c = 4*asset + gate   (orig column g = gate*128 + asset)
__global__ __launch_bounds__(256) void init_kernel(const float* __restrict__ x,
                                                   const float* __restrict__ Wih,
                                                   const float* __restrict__ Whh,
                                                   const float* __restrict__ b_ih,
                                                   const float* __restrict__ b_hh) {
    if (blockIdx.x < NS) {
        const int s = blockIdx.x;
        const float* xs = x + (size_t)s * (NB * NH);
        float sum = 0.f, sq = 0.f;
        for (int i = threadIdx.x; i < NB * NH; i += 256) {
            float v = xs[i];
            sum += v; sq += v * v;
        }
        __shared__ float s1[256], s2[256];
        s1[threadIdx.x] = sum; s2[threadIdx.x] = sq;
        __syncthreads();
        for (int o = 128; o > 0; o >>= 1) {
            if (threadIdx.x < o) {
                s1[threadIdx.x] += s1[threadIdx.x + o];
                s2[threadIdx.x] += s2[threadIdx.x + o];
            }
            __syncthreads();
        }
        if (threadIdx.x == 0) {
            const float invn = 1.f / (float)(NB * NH);
            float mean = s1[0] * invn;
            float var = s2[0] * invn - mean * mean;
            g_mean[s] = mean;
            g_istd[s] = 1.f / sqrtf(var + 1e-5f);
        }
    } else {
        int idx = (blockIdx.x - NS) * 256 + threadIdx.x;   // [0, 65536)
        int g = idx >> 7, k = idx & 127;
        int c = 4 * (g & 127) + (g >> 7);
        g_WihT[k * NG + c] = Wih[(size_t)g * NH + k];
        g_Whh4[(k >> 2) * (NG * 4) + c * 4 + (k & 3)] = Whh[(size_t)g * NH + k];
        if (idx < NG) {
            float s = 0.f;
            for (int kk = 0; kk < NH; kk++) s += Wih[(size_t)idx * NH + kk];
            int cc = 4 * (idx & 127) + (idx >> 7);
            g_rowsumW[cc] = s;
            g_bihP[cc] = b_ih[idx];
            g_bhhP[cc] = b_hh[idx];
        }
    }
}

// ---------------- 3) xg = IN(x) @ WihT + b_ih (IN folded into epilogue) --------
// 128x128 tile, 8x8 micro-tile via f32x2 packed FMA, k-step 16, 2 CTAs/SM.
__global__ __launch_bounds__(256, 2) void xg_gemm_kernel(const float* __restrict__ x,
                                                         const float* __restrict__ in_w,
                                                         const float* __restrict__ in_b) {
    __shared__ float As[16][132];   // [k][m]
    __shared__ float Bs[16][132];   // [k][c]
    const int m0 = blockIdx.x * 128;
    const int g0 = blockIdx.y * 128;
    const int tid = threadIdx.x;
    const int tx = tid & 15, ty = tid >> 4;
    ull2f acc2[8][4];
#pragma unroll
    for (int i = 0; i < 8; i++)
#pragma unroll
        for (int j = 0; j < 4; j++) acc2[i][j] = 0ull;   // (0.f, 0.f)

    for (int k0 = 0; k0 < 128; k0 += 16) {
#pragma unroll
        for (int r = 0; r < 2; r++) {
            int li = tid + r * 256;            // [0,512): A = 128 rows x 16 k
            int row = li >> 2, c4 = li & 3;
            float4 v = *(const float4*)(x + (size_t)(m0 + row) * NH + k0 + c4 * 4);
            As[c4 * 4 + 0][row] = v.x;
            As[c4 * 4 + 1][row] = v.y;
            As[c4 * 4 + 2][row] = v.z;
            As[c4 * 4 + 3][row] = v.w;
        }
#pragma unroll
        for (int r = 0; r < 2; r++) {
            int li = tid + r * 256;            // [0,512): B = 16 k x 128 c
            int kk = li >> 5, g4 = li & 31;
            float4 v = *(const float4*)(g_WihT + (size_t)(k0 + kk) * NG + g0 + g4 * 4);
            *(float4*)&Bs[kk][g4 * 4] = v;
        }
        __syncthreads();
#pragma unroll
        for (int k = 0; k < 16; k++) {
            float av[8];
            *(float4*)&av[0] = *(const float4*)&As[k][ty * 8];
            *(float4*)&av[4] = *(const float4*)&As[k][ty * 8 + 4];
            F4U b0_, b1_;
            b0_.v = *(const float4*)&Bs[k][tx * 4];
            b1_.v = *(const float4*)&Bs[k][64 + tx * 4];
            ull2f bv2[4] = { b0_.u[0], b0_.u[1], b1_.u[0], b1_.u[1] };
#pragma unroll
            for (int i = 0; i < 8; i++) {
                ull2f ad = dupf2(av[i]);
#pragma unroll
                for (int j = 0; j < 4; j++) acc2[i][j] = ffma2(ad, bv2[j], acc2[i][j]);
            }
        }
        __syncthreads();
    }
    const int s = m0 >> 9;                      // 512 rows per time step
    const float iw = in_w[0], ib = in_b[0];
    const float alpha = iw * g_istd[s];
    const float gamma = ib - alpha * g_mean[s];
    float base[8];
#pragma unroll
    for (int j = 0; j < 8; j++) {
        int gi = (j < 4) ? (g0 + tx * 4 + j) : (g0 + 64 + tx * 4 + (j - 4));
        base[j] = gamma * g_rowsumW[gi] + g_bihP[gi];
    }
#pragma unroll
    for (int i = 0; i < 8; i++) {
        int m = m0 + ty * 8 + i;
        float a0, a1, a2, a3, a4, a5, a6, a7;
        unpackf2(acc2[i][0], a0, a1);
        unpackf2(acc2[i][1], a2, a3);
        unpackf2(acc2[i][2], a4, a5);
        unpackf2(acc2[i][3], a6, a7);
        float4 o0, o1;
        o0.x = fmaf(alpha, a0, base[0]);
        o0.y = fmaf(alpha, a1, base[1]);
        o0.z = fmaf(alpha, a2, base[2]);
        o0.w = fmaf(alpha, a3, base[3]);
        o1.x = fmaf(alpha, a4, base[4]);
        o1.y = fmaf(alpha, a5, base[5]);
        o1.z = fmaf(alpha, a6, base[6]);
        o1.w = fmaf(alpha, a7, base[7]);
        *(float4*)(g_xg + (size_t)m * NG + g0 + tx * 4) = o0;
        *(float4*)(g_xg + (size_t)m * NG + g0 + 64 + tx * 4) = o1;
    }
}

// ---------------- 4) LSTM: 4 rows/CTA, gate-interleaved, xg prefetch -----------
__global__ __launch_bounds__(512) void lstm_kernel() {
    const int b0 = blockIdx.x * 4;
    const int c = threadIdx.x;                 // permuted column 0..511
    const int lane = c & 31;
    const int kr = lane & 3;                   // row this lane activates
    const int asset = c >> 2;                  // asset this lane activates
    __shared__ float2 h2[2][2][128];           // [buf][rowpair][k]
    ((float*)h2[0])[(kr >> 1) * 256 + asset * 2 + (kr & 1)] = 0.f;
    float c_reg = 0.f;
    const float bhh = g_bhhP[c];
    const float4* __restrict__ w4 = ((const float4*)g_Whh4) + c;   // row k4: +k4*NG
    __syncthreads();

    // prefetch xg for t = 0
    float x0, x1, x2, x3;
    {
        const float* xp = g_xg + (size_t)b0 * NG + c;
        x0 = xp[0]; x1 = xp[NG]; x2 = xp[2 * NG]; x3 = xp[3 * NG];
    }

    for (int t = 0; t < NS; t++) {
        const int p = t & 1;
        ull2f acc01 = packf2(x0 + bhh, x1 + bhh);
        ull2f acc23 = packf2(x2 + bhh, x3 + bhh);
        // issue next step's xg loads now; consumed after the barrier
        {
            int tn = (t + 1 < NS) ? t + 1 : t;
            const float* xp = g_xg + ((size_t)tn * NB + b0) * NG + c;
            x0 = xp[0]; x1 = xp[NG]; x2 = xp[2 * NG]; x3 = xp[3 * NG];
        }
#pragma unroll
        for (int k4 = 0; k4 < 32; k4++) {
            float4 w = w4[(size_t)k4 * NG];
            F4U A, B, C, D;
            A.v = *(const float4*)&h2[p][0][k4 * 4];        // rows(0,1) @ k, k+1
            B.v = *(const float4*)&h2[p][0][k4 * 4 + 2];    // rows(0,1) @ k+2, k+3
            C.v = *(const float4*)&h2[p][1][k4 * 4];        // rows(2,3) @ k, k+1
            D.v = *(const float4*)&h2[p][1][k4 * 4 + 2];
            ull2f w0 = dupf2(w.x), w1 = dupf2(w.y), w2 = dupf2(w.z), w3 = dupf2(w.w);
            acc01 = ffma2(A.u[0], w0, acc01);
            acc01 = ffma2(A.u[1], w1, acc01);
            acc01 = ffma2(B.u[0], w2, acc01);
            acc01 = ffma2(B.u[1], w3, acc01);
            acc23 = ffma2(C.u[0], w0, acc23);
            acc23 = ffma2(C.u[1], w1, acc23);
            acc23 = ffma2(D.u[0], w2, acc23);
            acc23 = ffma2(D.u[1], w3, acc23);
        }
        float r0, r1, r2, r3;
        unpackf2(acc01, r0, r1);
        unpackf2(acc23, r2, r3);

        // intra-quad gate exchange: lanes base..base+3 hold gates i,f,g,o of one asset
        const int base = lane & ~3;
        float i0 = __shfl_sync(FMASK, r0, base),     i1 = __shfl_sync(FMASK, r1, base);
        float i2 = __shfl_sync(FMASK, r2, base),     i3 = __shfl_sync(FMASK, r3, base);
        float f0 = __shfl_sync(FMASK, r0, base + 1), f1 = __shfl_sync(FMASK, r1, base + 1);
        float f2 = __shfl_sync(FMASK, r2, base + 1), f3 = __shfl_sync(FMASK, r3, base + 1);
        float g0 = __shfl_sync(FMASK, r0, base + 2), g1 = __shfl_sync(FMASK, r1, base + 2);
        float g2 = __shfl_sync(FMASK, r2, base + 2), g3 = __shfl_sync(FMASK, r3, base + 2);
        float o0 = __shfl_sync(FMASK, r0, base + 3), o1 = __shfl_sync(FMASK, r1, base + 3);
        float o2 = __shfl_sync(FMASK, r2, base + 3), o3 = __shfl_sync(FMASK, r3, base + 3);
        float vi = (kr == 0) ? i0 : (kr == 1) ? i1 : (kr == 2) ? i2 : i3;
        float vf = (kr == 0) ? f0 : (kr == 1) ? f1 : (kr == 2) ? f2 : f3;
        float vg = (kr == 0) ? g0 : (kr == 1) ? g1 : (kr == 2) ? g2 : g3;
        float vo = (kr == 0) ? o0 : (kr == 1) ? o1 : (kr == 2) ? o2 : o3;

        float cn = sigf(vf) * c_reg + sigf(vi) * tanhf(vg);
        float hn = sigf(vo) * tanhf(cn);
        c_reg = cn;
        ((float*)h2[p ^ 1])[(kr >> 1) * 256 + asset * 2 + (kr & 1)] = hn;
        g_hs[((size_t)t * NB + b0 + kr) * NH + asset] = hn;
        __syncthreads();
    }
}

// ---------------- 5) fused mean-center + cov (diag-mixed) + Q = cov@cov --------
// Both GEMM loops use packed FFMA2; regs capped for 2 CTAs/SM.
__global__ __launch_bounds__(256, 2) void covq_kernel() {
    extern __shared__ float sm[];
    float* covs = sm;                 // 128*132
    float* Ms = sm + 128 * 132;       // 32*132
    __shared__ float psum[256];
    __shared__ float mean_s[128];
    const int s = blockIdx.x, tid = threadIdx.x;
    const float* __restrict__ hs = g_hs + (size_t)s * NB * NH;

    {
        int col = tid & 127, part = tid >> 7;
        float a = 0.f;
        for (int l = part * 256; l < part * 256 + 256; l++) a += hs[(size_t)l * NH + col];
        psum[tid] = a;
        __syncthreads();
        if (tid < 128) mean_s[tid] = (psum[tid] + psum[tid + 128]) * (1.f / NB);
        __syncthreads();
    }

    const int tx = tid & 15, ty = tid >> 4;
    ull2f acc2[8][4];
#pragma unroll
    for (int i = 0; i < 8; i++)
#pragma unroll
        for (int j = 0; j < 4; j++) acc2[i][j] = 0ull;

    for (int l0 = 0; l0 < NB; l0 += 32) {
#pragma unroll
        for (int r = 0; r < 16; r++) {
            int li = tid + r * 256;            // [0,4096)
            int row = li >> 7, col = li & 127;
            Ms[row * 132 + col] = hs[(size_t)(l0 + row) * NH + col] - mean_s[col];
        }
        __syncthreads();
#pragma unroll
        for (int k = 0; k < 32; k++) {
            float av[8];
            *(float4*)&av[0] = *(const float4*)&Ms[k * 132 + ty * 8];
            *(float4*)&av[4] = *(const float4*)&Ms[k * 132 + ty * 8 + 4];
            F4U b0_, b1_;
            b0_.v = *(const float4*)&Ms[k * 132 + tx * 8];
            b1_.v = *(const float4*)&Ms[k * 132 + tx * 8 + 4];
            ull2f bv2[4] = { b0_.u[0], b0_.u[1], b1_.u[0], b1_.u[1] };
#pragma unroll
            for (int i = 0; i < 8; i++) {
                ull2f ad = dupf2(av[i]);
#pragma unroll
                for (int j = 0; j < 4; j++) acc2[i][j] = ffma2(ad, bv2[j], acc2[i][j]);
            }
        }
        __syncthreads();
    }

    const float inv = 1.f / (float)(NB - 1);
#pragma unroll
    for (int i = 0; i < 8; i++) {
        float a[8];
        unpackf2(acc2[i][0], a[0], a[1]);
        unpackf2(acc2[i][1], a[2], a[3]);
        unpackf2(acc2[i][2], a[4], a[5]);
        unpackf2(acc2[i][3], a[6], a[7]);
#pragma unroll
        for (int j = 0; j < 8; j++) {
            int a_ = ty * 8 + i, b_ = tx * 8 + j;
            float v = a[j] * inv;
            if (a_ != b_) v *= 0.5f;
            covs[a_ * 132 + b_] = v;
        }
    }
    __syncthreads();

    ull2f q2[8][4];
#pragma unroll
    for (int i = 0; i < 8; i++)
#pragma unroll
        for (int j = 0; j < 4; j++) q2[i][j] = 0ull;
    for (int b = 0; b < 128; b++) {
        float av[8];
        *(float4*)&av[0] = *(const float4*)&covs[b * 132 + ty * 8];
        *(float4*)&av[4] = *(const float4*)&covs[b * 132 + ty * 8 + 4];
        F4U c0_, c1_;
        c0_.v = *(const float4*)&covs[b * 132 + tx * 8];
        c1_.v = *(const float4*)&covs[b * 132 + tx * 8 + 4];
        ull2f cv2[4] = { c0_.u[0], c0_.u[1], c1_.u[0], c1_.u[1] };
#pragma unroll
        for (int i = 0; i < 8; i++) {
            ull2f ad = dupf2(av[i]);
#pragma unroll
            for (int j = 0; j < 4; j++) q2[i][j] = ffma2(ad, cv2[j], q2[i][j]);
        }
    }
    float* Qout = g_Q + (size_t)s * NH * NH;
#pragma unroll
    for (int i = 0; i < 8; i++) {
        float q[8];
        unpackf2(q2[i][0], q[0], q[1]);
        unpackf2(q2[i][1], q[2], q[3]);
        unpackf2(q2[i][2], q[4], q[5]);
        unpackf2(q2[i][3], q[6], q[7]);
#pragma unroll
        for (int j = 0; j < 8; j++)
            Qout[(size_t)(ty * 8 + i) * NH + tx * 8 + j] = q[j];
    }
}

// ---------------- 6) power iteration + FISTA, ONE warp per s -------------------
// Element mapping: lane owns elements e = lane*4 + j  (j = 0..3).
// Matvec: z broadcast via shared memory (1 STS.128 + 32 uniform LDS.128); Q rows
// read as coalesced LDG.128, accumulated with FFMA2.
__device__ __forceinline__ void matvec128s(const float* __restrict__ Q, int lane,
                                           const float z[4], float y[4],
                                           float4* __restrict__ zsm) {
    zsm[lane] = make_float4(z[0], z[1], z[2], z[3]);
    __syncwarp();
    ull2f a0 = 0ull, a1 = 0ull;
#pragma unroll 8
    for (int m = 0; m < 32; m++) {
        float4 zz = zsm[m];                     // uniform address -> broadcast
#pragma unroll
        for (int j = 0; j < 4; j++) {
            float zb = (j == 0) ? zz.x : (j == 1) ? zz.y : (j == 2) ? zz.z : zz.w;
            F4U q;
            q.v = *(const float4*)(Q + (size_t)(m * 4 + j) * NH + lane * 4);
            ull2f zd = dupf2(zb);
            a0 = ffma2(q.u[0], zd, a0);
            a1 = ffma2(q.u[1], zd, a1);
        }
    }
    __syncwarp();                               // zsm free for next overwrite
    unpackf2(a0, y[0], y[1]);
    unpackf2(a1, y[2], y[3]);
}

__global__ __launch_bounds__(32) void solve_kernel(float* __restrict__ out) {
    const int s = blockIdx.x;
    const int lane = threadIdx.x;
    const float* __restrict__ Q = g_Q + (size_t)s * NH * NH;
    __shared__ float4 zsm[32];
    const int sub = lane & 7;
    const float fgrp = (float)((lane >> 3) + 1);

    // power iteration for the top eigenvalue
    float bb[4];
#pragma unroll
    for (int j = 0; j < 4; j++) bb[j] = 0.08838834764831843f;   // 1/sqrt(128)
    for (int it = 0; it < 30; it++) {
        float y[4];
        matvec128s(Q, lane, bb, y, zsm);
        float nn = (y[0] * y[0] + y[1] * y[1]) + (y[2] * y[2] + y[3] * y[3]);
        nn = warpSum(nn);
        float invn = 1.f / (sqrtf(nn) + 1e-12f);
#pragma unroll
        for (int j = 0; j < 4; j++) bb[j] = y[j] * invn;
    }
    float lam;
    {
        float y[4];
        matvec128s(Q, lane, bb, y, zsm);
        float d = (bb[0] * y[0] + bb[1] * y[1]) + (bb[2] * y[2] + bb[3] * y[3]);
        lam = warpSum(d);
    }
    const float step = 1.f / (lam + 1e-8f);

    // FISTA with warm-started projection bracket.
    // tau is 1-Lipschitz in v: tau*(v+d) in [tau*(v)+min d, tau*(v)+max d]
    // (clip is monotone). vrp = previous vr; tau_prev = its exact dual.
    // Init: vrp = 1/128 uniform => tau_prev = 0 exactly.
    float w[4], z[4];
#pragma unroll
    for (int j = 0; j < 4; j++) { w[j] = 1.f / 128.f; z[j] = w[j]; }
    float vrp[16];
#pragma unroll
    for (int k = 0; k < 16; k++) vrp[k] = 1.f / 128.f;
    float tau_prev = 0.f;
    float t = 1.f;
    for (int it = 0; it < 300; it++) {
        float g[4];
        matvec128s(Q, lane, z, g, zsm);
        float v[4];
#pragma unroll
        for (int j = 0; j < 4; j++) v[j] = z[j] - step * g[j];

        // replicate so each 8-lane group holds all 128 elements.
        // vr[q*4+j] = v[j] from source lane (sub + 8q); register index j is
        // loop-uniform (shuffle returns the SOURCE lane's v[j]).
        float vr[16];
#pragma unroll
        for (int q = 0; q < 4; q++)
#pragma unroll
            for (int j = 0; j < 4; j++)
                vr[q * 4 + j] = __shfl_sync(FMASK, v[j], sub + 8 * q);

        // warm bracket: min/max of (vr - vrp), pairwise tree + group reduce
        float mnD, mxD;
        {
            float d_[16];
#pragma unroll
            for (int k = 0; k < 16; k++) d_[k] = vr[k] - vrp[k];
            float m0 = fminf(d_[0], d_[1]),  m1 = fminf(d_[2], d_[3]);
            float m2 = fminf(d_[4], d_[5]),  m3 = fminf(d_[6], d_[7]);
            float m4 = fminf(d_[8], d_[9]),  m5 = fminf(d_[10], d_[11]);
            float m6 = fminf(d_[12], d_[13]), m7 = fminf(d_[14], d_[15]);
            mnD = fminf(fminf(fminf(m0, m1), fminf(m2, m3)),
                        fminf(fminf(m4, m5), fminf(m6, m7)));
            float x0 = fmaxf(d_[0], d_[1]),  x1 = fmaxf(d_[2], d_[3]);
            float x2 = fmaxf(d_[4], d_[5]),  x3 = fmaxf(d_[6], d_[7]);
            float x4 = fmaxf(d_[8], d_[9]),  x5 = fmaxf(d_[10], d_[11]);
            float x6 = fmaxf(d_[12], d_[13]), x7 = fmaxf(d_[14], d_[15]);
            mxD = fmaxf(fmaxf(fmaxf(x0, x1), fmaxf(x2, x3)),
                        fmaxf(fmaxf(x4, x5), fmaxf(x6, x7)));
        }
        mnD = grpMin8(mnD);
        mxD = grpMax8(mxD);
        float lo = tau_prev + mnD - 1e-3f;
        float hi = tau_prev + mxD + 1e-3f;

        // 4-probe parallel interval search: 5x shrink per iter, 5 iters.
        // Typical warm width ~2e-3 => tau0 error ~6e-7; early iters (width
        // ~0.05) => ~1.6e-5, absorbed by the exact refit + FISTA contraction.
        for (int bi = 0; bi < 5; bi++) {
            float delta = 0.2f * (hi - lo);
            float mid = fmaf(delta, fgrp, lo);
            float c0 = clamp1(vr[0] - mid) + clamp1(vr[1] - mid);
            float c1 = clamp1(vr[2] - mid) + clamp1(vr[3] - mid);
            float c2 = clamp1(vr[4] - mid) + clamp1(vr[5] - mid);
            float c3 = clamp1(vr[6] - mid) + clamp1(vr[7] - mid);
            float c4 = clamp1(vr[8] - mid) + clamp1(vr[9] - mid);
            float c5 = clamp1(vr[10] - mid) + clamp1(vr[11] - mid);
            float c6 = clamp1(vr[12] - mid) + clamp1(vr[13] - mid);
            float c7 = clamp1(vr[14] - mid) + clamp1(vr[15] - mid);
            float ss = ((c0 + c1) + (c2 + c3)) + ((c4 + c5) + (c6 + c7));
            ss = grpSum8(ss);
            unsigned m = __ballot_sync(FMASK, ss > 1.f);
            int cnt = __popc(m) >> 3;               // # probes with s(mid) > 1
            float nlo = fmaf(delta, (float)cnt, lo);
            float nhi = fmaf(delta, (float)(cnt + 1), lo);
            lo = (cnt == 0) ? lo : nlo;
            hi = (cnt == 4) ? hi : nhi;
        }
        float tau0 = 0.5f * (lo + hi);

        // exact active-set refit (same classification as reference);
        // pairwise-tree local sums + 3-level group reduce per quantity
        float csl[16], vsl[16], bsl[16];
#pragma unroll
        for (int k = 0; k < 16; k++) {
            float w0 = clamp1(vr[k] - tau0);
            bool inter = fabsf(w0) < 1.f - 1e-6f;
            csl[k] = inter ? 1.f : 0.f;
            vsl[k] = inter ? vr[k] : 0.f;
            bsl[k] = inter ? 0.f : w0;
        }
        float cs, vs, bs;
        {
            float a0 = (csl[0] + csl[1]) + (csl[2] + csl[3]);
            float a1 = (csl[4] + csl[5]) + (csl[6] + csl[7]);
            float a2 = (csl[8] + csl[9]) + (csl[10] + csl[11]);
            float a3 = (csl[12] + csl[13]) + (csl[14] + csl[15]);
            cs = (a0 + a1) + (a2 + a3);
            float b0 = (vsl[0] + vsl[1]) + (vsl[2] + vsl[3]);
            float b1 = (vsl[4] + vsl[5]) + (vsl[6] + vsl[7]);
            float b2 = (vsl[8] + vsl[9]) + (vsl[10] + vsl[11]);
            float b3 = (vsl[12] + vsl[13]) + (vsl[14] + vsl[15]);
            vs = (b0 + b1) + (b2 + b3);
            float d0 = (bsl[0] + bsl[1]) + (bsl[2] + bsl[3]);
            float d1 = (bsl[4] + bsl[5]) + (bsl[6] + bsl[7]);
            float d2 = (bsl[8] + bsl[9]) + (bsl[10] + bsl[11]);
            float d3 = (bsl[12] + bsl[13]) + (bsl[14] + bsl[15]);
            bs = (d0 + d1) + (d2 + d3);
        }
        cs = grpSum8(cs);
        vs = grpSum8(vs);
        bs = grpSum8(bs);
        float tau = (vs - (1.f - bs)) / fmaxf(cs, 1.f);
        float wn[4];
#pragma unroll
        for (int j = 0; j < 4; j++) wn[j] = clamp1(v[j] - tau);

        // bitwise fixed-point early exit: if wn == w AND z == wn (all lanes),
        // then z_next = wn and the next iterate recomputes the identical v,
        // hence identical wn -- every remaining iteration is a no-op.
        {
            bool moved = (wn[0] != w[0]) || (wn[1] != w[1]) ||
                         (wn[2] != w[2]) || (wn[3] != w[3]) ||
                         (z[0] != wn[0]) || (z[1] != wn[1]) ||
                         (z[2] != wn[2]) || (z[3] != wn[3]);
            if (__ballot_sync(FMASK, moved) == 0u) break;
        }

        // save warm-start state
#pragma unroll
        for (int k = 0; k < 16; k++) vrp[k] = vr[k];
        tau_prev = tau;

        float tn = 0.5f * (1.f + sqrtf(1.f + 4.f * t * t));
        float coef = (t - 1.f) / tn;
#pragma unroll
        for (int j = 0; j < 4; j++) {
            z[j] = wn[j] + coef * (wn[j] - w[j]);
            w[j] = wn[j];
        }
        t = tn;
    }
#pragma unroll
    for (int j = 0; j < 4; j++)
        out[(size_t)s * NH + lane * 4 + j] = w[j];
}

// ---------------- launch: single stream --------------------------------------
extern "C" void kernel_launch(void* const* d_in, const int* in_sizes, int n_in,
                              void* d_out, int out_size) {
    const float* x    = (const float*)d_in[0];
    const float* in_w = (const float*)d_in[1];
    const float* in_b = (const float*)d_in[2];
    const float* W_ih = (const float*)d_in[3];
    const float* W_hh = (const float*)d_in[4];
    const float* b_ih = (const float*)d_in[5];
    const float* b_hh = (const float*)d_in[6];
    float* out = (float*)d_out;

    init_kernel<<<512, 256>>>(x, W_ih, W_hh, b_ih, b_hh);
    xg_gemm_kernel<<<dim3(1024, 4), 256>>>(x, in_w, in_b);
    lstm_kernel<<<NB / 4, 512>>>();

    const int covq_smem = (128 * 132 + 32 * 132) * (int)sizeof(float);  // 84480 B
    cudaFuncSetAttribute(covq_kernel, cudaFuncAttributeMaxDynamicSharedMemorySize, covq_smem);
    covq_kernel<<<NS, 256, covq_smem>>>();

    solve_kernel<<<NS, 32>>>(out);
}